// round 13
// baseline (speedup 1.0000x reference)
#include <cuda_runtime.h>
#include <cuda_bf16.h>

// ROIRotate: bilinear crop-and-resize of axis-aligned boxes from an NHWC
// feature map.
//
// Shapes (static):
//   feature_map: (8, 128, 128, 32) fp32  (~16.7 MB, L2-resident)
//   boxes:       (2048, 9) fp32
//   box_indices: (2048,) int32 (harness downcasts the reference's int64)
//   max_width:   64
// Output: crops (2048, 8, 64, 32) fp32 + padded_width (2048,) fp32, flat.
//
// Single fused kernel. Block = 256 threads = 32 consecutive u positions of
// ONE (box, v) row (8 channel-quad lanes per position). Thread 0 computes
// the per-box params (division, width clip) once into shared memory; all
// threads then do 2 FMAs for sample coords + 4 gathers (LDG.128, complete
// 128B lines per warp -> minimal L1 wavefronts) + 1 streaming store.

#define ROI_HEIGHT 8
#define ROI_MAXW   64
#define ROI_NBOX   2048
#define FM_N       8
#define FM_H       128
#define FM_W       128
#define FM_C       32

// threads: one per (box, v, u, channel-quad). quads = FM_C/4 = 8.
// total = 2048 * 8 * 64 * 8 = 8,388,608 -> 32768 blocks of 256.
// block id = b*16 + v*2 + uhalf
__global__ __launch_bounds__(256)
void roi_rotate_kernel(const float* __restrict__ fm,
                       const float* __restrict__ boxes,
                       const int* __restrict__ bidx,
                       float* __restrict__ out)
{
    __shared__ float sp[8];  // x1, y1, du_x, du_y, dv_x, dv_y, width, n bits

    int blk   = blockIdx.x;
    int uhalf = blk & 1;
    int v     = (blk >> 1) & (ROI_HEIGHT - 1);
    int b     = blk >> 4;

    if (threadIdx.x == 0) {
        const float* bp = boxes + b * 9;
        float x1 = bp[0] * 0.25f, y1 = bp[1] * 0.25f;
        float x2 = bp[2] * 0.25f, y2 = bp[3] * 0.25f;
        float x4 = bp[6] * 0.25f, y4 = bp[7] * 0.25f;

        float box_w = x2 - x1;
        float box_h = y4 - y1;
        float width = (float)ROI_HEIGHT * box_w / fmaxf(box_h, 1e-6f);
        width = fminf(fmaxf(width, 1.0f), (float)ROI_MAXW);
        float inv_w = 1.0f / width;

        sp[0] = x1;
        sp[1] = y1;
        sp[2] = (x2 - x1) * inv_w;
        sp[3] = (y2 - y1) * inv_w;
        sp[4] = (x4 - x1) * (1.0f / ROI_HEIGHT);
        sp[5] = (y4 - y1) * (1.0f / ROI_HEIGHT);
        sp[6] = width;
        sp[7] = __int_as_float(bidx[b]);

        // padded_width, once per box (the v=0, uhalf=0 block)
        if ((blk & 15) == 0) {
            out[(size_t)ROI_NBOX * ROI_HEIGHT * ROI_MAXW * FM_C + b] =
                (float)ROI_MAXW - width;
        }
    }
    __syncthreads();

    int quad = threadIdx.x & 7;            // channel quad 0..7 (16 B)
    int u    = (uhalf << 5) + (threadIdx.x >> 3);

    float x1   = sp[0], y1   = sp[1];
    float du_x = sp[2], du_y = sp[3];
    float dv_x = sp[4], dv_y = sp[5];
    float width = sp[6];
    int   n     = __float_as_int(sp[7]);

    float4 r = make_float4(0.f, 0.f, 0.f, 0.f);

    float uf = (float)u, vf = (float)v;

    if (uf < width) {
        float sx = fmaf(uf, du_x, fmaf(vf, dv_x, x1));
        float sy = fmaf(uf, du_y, fmaf(vf, dv_y, y1));

        float fx0 = floorf(sx);
        float fy0 = floorf(sy);
        float wx = sx - fx0;
        float wy = sy - fy0;

        int x0i = min(max((int)fx0, 0), FM_W - 1);
        int x1i = min(x0i + 1, FM_W - 1);
        int y0i = min(max((int)fy0, 0), FM_H - 1);
        int y1i = min(y0i + 1, FM_H - 1);

        int co = quad << 2;   // 4 floats = 16 B per lane
        const float* row0 = fm + (((size_t)(n * FM_H + y0i) * FM_W) << 5) + co;
        const float* row1 = fm + (((size_t)(n * FM_H + y1i) * FM_W) << 5) + co;

        float4 g00 = *(const float4*)(row0 + ((size_t)x0i << 5));
        float4 g01 = *(const float4*)(row0 + ((size_t)x1i << 5));
        float4 g10 = *(const float4*)(row1 + ((size_t)x0i << 5));
        float4 g11 = *(const float4*)(row1 + ((size_t)x1i << 5));

        float w00 = (1.f - wy) * (1.f - wx);
        float w01 = (1.f - wy) * wx;
        float w10 = wy * (1.f - wx);
        float w11 = wy * wx;

        r.x = fmaf(w00, g00.x, fmaf(w01, g01.x, fmaf(w10, g10.x, w11 * g11.x)));
        r.y = fmaf(w00, g00.y, fmaf(w01, g01.y, fmaf(w10, g10.y, w11 * g11.y)));
        r.z = fmaf(w00, g00.z, fmaf(w01, g01.z, fmaf(w10, g10.z, w11 * g11.z)));
        r.w = fmaf(w00, g00.w, fmaf(w01, g01.w, fmaf(w10, g10.w, w11 * g11.w)));
    }

    // Coalesced streaming store: block covers 32 consecutive 128B output rows.
    // __stcs: don't let the 134MB output evict the L2-resident feature map.
    size_t pos = ((size_t)(b * ROI_HEIGHT + v) << 6) + (size_t)u;
    __stcs((float4*)(out + (pos << 5) + (quad << 2)), r);
}

extern "C" void kernel_launch(void* const* d_in, const int* in_sizes, int n_in,
                              void* d_out, int out_size)
{
    const float* fm    = (const float*)d_in[0];
    const float* boxes = (const float*)d_in[1];
    const int*   bidx  = (const int*)d_in[2];
    float*       out   = (float*)d_out;

    const int total = ROI_NBOX * ROI_HEIGHT * ROI_MAXW * (FM_C / 4); // 8,388,608
    roi_rotate_kernel<<<total / 256, 256>>>(fm, boxes, bidx, out);
}

// round 15
// speedup vs baseline: 1.0535x; 1.0535x over previous
#include <cuda_runtime.h>
#include <cuda_bf16.h>

// ROIRotate: bilinear crop-and-resize of axis-aligned boxes from an NHWC
// feature map.
//
// Shapes (static):
//   feature_map: (8, 128, 128, 32) fp32  (~16.7 MB, L2-resident)
//   boxes:       (2048, 9) fp32
//   box_indices: (2048,) int32 (harness downcasts the reference's int64)
//   max_width:   64
// Output: crops (2048, 8, 64, 32) fp32 + padded_width (2048,) fp32, flat.
//
// Single kernel, warp-cooperative box prep (NO block barrier — R12 showed a
// __syncthreads on a 1-thread producer serializes every block). Each warp
// covers 4 consecutive u positions of one (box, v): lanes 0..8 load one box
// element each, shfl-broadcast, then all lanes compute the cheap width math
// redundantly (same warp issue cost as lane-0-only). Main body: 2 FMAs for
// sample coords + 4 gathers (LDG.128 covering complete 128B lines -> minimal
// L1 wavefronts) + 1 coalesced streaming store (__stcs keeps the feature map
// L2-resident).

#define ROI_HEIGHT 8
#define ROI_MAXW   64
#define ROI_NBOX   2048
#define FM_N       8
#define FM_H       128
#define FM_W       128
#define FM_C       32

// threads: one per (box, v, u, channel-quad). quads = FM_C/4 = 8.
// total = 2048 * 8 * 64 * 8 = 8,388,608 -> 32768 blocks of 256.
__global__ __launch_bounds__(256)
void roi_rotate_kernel(const float* __restrict__ fm,
                       const float* __restrict__ boxes,
                       const int* __restrict__ bidx,
                       float* __restrict__ out)
{
    int gid  = blockIdx.x * blockDim.x + threadIdx.x;
    int lane = threadIdx.x & 31;
    int quad = gid & 7;          // channel quad 0..7 (16 B)
    int pos  = gid >> 3;         // (b, v, u); a warp = 4 consecutive pos
    int u    = pos & (ROI_MAXW - 1);
    int bv   = pos >> 6;
    int v    = bv & (ROI_HEIGHT - 1);
    int b    = bv >> 3;          // same for all 32 lanes of a warp

    // ---- warp-cooperative box param fetch (no barrier) ----
    const float* bp = boxes + b * 9;
    float el = 0.0f;
    if (lane < 8) el = bp[lane];           // one coalesced LDG, lanes 0..7
    int nl = 0;
    if (lane == 0) nl = bidx[b];           // predicated scalar LDG

    float x1 = __shfl_sync(0xffffffffu, el, 0) * 0.25f;
    float y1 = __shfl_sync(0xffffffffu, el, 1) * 0.25f;
    float x2 = __shfl_sync(0xffffffffu, el, 2) * 0.25f;
    float y2 = __shfl_sync(0xffffffffu, el, 3) * 0.25f;
    float x4 = __shfl_sync(0xffffffffu, el, 6) * 0.25f;
    float y4 = __shfl_sync(0xffffffffu, el, 7) * 0.25f;
    int   n  = __shfl_sync(0xffffffffu, nl, 0);

    float box_w = x2 - x1;
    float box_h = y4 - y1;
    float width = (float)ROI_HEIGHT * box_w / fmaxf(box_h, 1e-6f);
    width = fminf(fmaxf(width, 1.0f), (float)ROI_MAXW);
    float inv_w = 1.0f / width;

    float du_x = (x2 - x1) * inv_w;
    float du_y = (y2 - y1) * inv_w;
    float dv_x = (x4 - x1) * (1.0f / ROI_HEIGHT);
    float dv_y = (y4 - y1) * (1.0f / ROI_HEIGHT);

    // ---- main body (identical to the 29.2us R8 kernel) ----
    float4 r = make_float4(0.f, 0.f, 0.f, 0.f);
    float uf = (float)u, vf = (float)v;

    if (uf < width) {
        float sx = fmaf(uf, du_x, fmaf(vf, dv_x, x1));
        float sy = fmaf(uf, du_y, fmaf(vf, dv_y, y1));

        int fx0 = __float2int_rd(sx);
        int fy0 = __float2int_rd(sy);
        float wx = sx - (float)fx0;
        float wy = sy - (float)fy0;

        int x0i = min(max(fx0, 0), FM_W - 1);
        int x1i = min(x0i + 1, FM_W - 1);
        int y0i = min(max(fy0, 0), FM_H - 1);
        int y1i = min(y0i + 1, FM_H - 1);

        int co = quad << 2;   // 4 floats = 16 B per lane
        const float* row0 = fm + (((size_t)(n * FM_H + y0i) * FM_W) << 5) + co;
        const float* row1 = fm + (((size_t)(n * FM_H + y1i) * FM_W) << 5) + co;

        float4 g00 = *(const float4*)(row0 + ((size_t)x0i << 5));
        float4 g01 = *(const float4*)(row0 + ((size_t)x1i << 5));
        float4 g10 = *(const float4*)(row1 + ((size_t)x0i << 5));
        float4 g11 = *(const float4*)(row1 + ((size_t)x1i << 5));

        float w00 = (1.f - wy) * (1.f - wx);
        float w01 = (1.f - wy) * wx;
        float w10 = wy * (1.f - wx);
        float w11 = wy * wx;

        r.x = fmaf(w00, g00.x, fmaf(w01, g01.x, fmaf(w10, g10.x, w11 * g11.x)));
        r.y = fmaf(w00, g00.y, fmaf(w01, g01.y, fmaf(w10, g10.y, w11 * g11.y)));
        r.z = fmaf(w00, g00.z, fmaf(w01, g01.z, fmaf(w10, g10.z, w11 * g11.z)));
        r.w = fmaf(w00, g00.w, fmaf(w01, g01.w, fmaf(w10, g10.w, w11 * g11.w)));
    }

    // Coalesced streaming store: consecutive gid -> consecutive 16B chunks.
    __stcs((float4*)(out + (((size_t)pos) << 5) + (quad << 2)), r);

    // padded_width, once per box
    if (u == 0 && v == 0 && quad == 0) {
        out[(size_t)ROI_NBOX * ROI_HEIGHT * ROI_MAXW * FM_C + b] =
            (float)ROI_MAXW - width;
    }
}

extern "C" void kernel_launch(void* const* d_in, const int* in_sizes, int n_in,
                              void* d_out, int out_size)
{
    const float* fm    = (const float*)d_in[0];
    const float* boxes = (const float*)d_in[1];
    const int*   bidx  = (const int*)d_in[2];
    float*       out   = (float*)d_out;

    const int total = ROI_NBOX * ROI_HEIGHT * ROI_MAXW * (FM_C / 4); // 8,388,608
    roi_rotate_kernel<<<total / 256, 256>>>(fm, boxes, bidx, out);
}

// round 16
// speedup vs baseline: 1.2097x; 1.1482x over previous
#include <cuda_runtime.h>
#include <cuda_bf16.h>

// ROIRotate: bilinear crop-and-resize of axis-aligned boxes from an NHWC
// feature map.
//
// Shapes (static):
//   feature_map: (8, 128, 128, 32) fp32  (~16.7 MB, L2-resident across graph replays)
//   boxes:       (2048, 9) fp32
//   box_indices: (2048,) int32 (harness downcasts the reference's int64)
//   max_width:   64
// Output: crops (2048, 8, 64, 32) fp32 + padded_width (2048,) fp32, flat.
//
// Two kernels (fusion attempts R12/R13/R15 all regressed — barrier or shfl
// serialization):
//   1. box_prep: per-box math -> 8-float param block + padded_width.
//   2. main: 8 lanes per sample position, 16 B of channels per lane
//      (one LDG.128 per corner per warp covering complete 128 B lines ->
//      minimal L1 wavefronts). NEW: clamp x0i/y0i to <=126 and saturate the
//      fractional weights so x1i==x0i+1, y1i==y0i+1 unconditionally. All four
//      corner gathers then share ONE base address with immediate offsets
//      (+0, +128B, +16KB, +16KB+128B), cutting the per-thread ALU chain.
//      Streaming stores (__stcs) keep the feature map L2-resident.

#define ROI_HEIGHT 8
#define ROI_MAXW   64
#define ROI_NBOX   2048
#define FM_N       8
#define FM_H       128
#define FM_W       128
#define FM_C       32

// Per-box param block: {x1, y1, du_x, du_y, dv_x, dv_y, width, n_as_float_bits}
__device__ __align__(32) float g_boxparams[ROI_NBOX * 8];

__global__ void box_prep_kernel(const float* __restrict__ boxes,
                                const int* __restrict__ bidx,
                                float* __restrict__ out)
{
    int b = blockIdx.x * blockDim.x + threadIdx.x;
    if (b >= ROI_NBOX) return;

    const float* bp = boxes + b * 9;
    float x1 = bp[0] * 0.25f, y1 = bp[1] * 0.25f;
    float x2 = bp[2] * 0.25f, y2 = bp[3] * 0.25f;
    float x4 = bp[6] * 0.25f, y4 = bp[7] * 0.25f;

    float box_w = x2 - x1;
    float box_h = y4 - y1;
    float width = (float)ROI_HEIGHT * box_w / fmaxf(box_h, 1e-6f);
    width = fminf(fmaxf(width, 1.0f), (float)ROI_MAXW);
    float inv_w = 1.0f / width;

    float* p = g_boxparams + b * 8;
    float4 p0 = make_float4(x1, y1, (x2 - x1) * inv_w, (y2 - y1) * inv_w);
    float4 p1 = make_float4((x4 - x1) * (1.0f / ROI_HEIGHT),
                            (y4 - y1) * (1.0f / ROI_HEIGHT),
                            width,
                            __int_as_float(bidx[b]));
    *(float4*)(p)     = p0;
    *(float4*)(p + 4) = p1;

    out[(size_t)ROI_NBOX * ROI_HEIGHT * ROI_MAXW * FM_C + b] =
        (float)ROI_MAXW - width;
}

// threads: one per (box, v, u, channel-quad). quads = FM_C/4 = 8.
// total = 2048 * 8 * 64 * 8 = 8,388,608
__global__ __launch_bounds__(256)
void roi_rotate_kernel(const float* __restrict__ fm,
                       float* __restrict__ out)
{
    int gid  = blockIdx.x * blockDim.x + threadIdx.x;
    int quad = gid & 7;          // channel quad 0..7 (16 B)
    int pos  = gid >> 3;         // (b, v, u)
    int u    = pos & (ROI_MAXW - 1);
    int bv   = pos >> 6;
    int v    = bv & (ROI_HEIGHT - 1);
    int b    = bv >> 3;

    const float* p = g_boxparams + b * 8;
    float4 p0 = *(const float4*)(p);      // x1, y1, du_x, du_y
    float4 p1 = *(const float4*)(p + 4);  // dv_x, dv_y, width, n bits

    float4 r = make_float4(0.f, 0.f, 0.f, 0.f);

    float uf = (float)u, vf = (float)v;

    if (uf < p1.z) {
        float sx = fmaf(uf, p0.z, fmaf(vf, p1.x, p0.x));
        float sy = fmaf(uf, p0.w, fmaf(vf, p1.y, p0.y));

        // Clamp the low corner to <=126 and saturate the fractional weight.
        // For fx0 == 127 the reference collapses to g(127) (both x taps equal);
        // x0i=126, wx=1 reproduces that exactly. sx,sy >= 0 by construction.
        int x0i = min(max(__float2int_rd(sx), 0), FM_W - 2);
        int y0i = min(max(__float2int_rd(sy), 0), FM_H - 2);
        float wx = __saturatef(sx - (float)x0i);
        float wy = __saturatef(sy - (float)y0i);

        int n  = __float_as_int(p1.w);
        // One base address; all four corners at immediate offsets.
        const float* base = fm
            + (((size_t)((n * FM_H + y0i) * FM_W + x0i)) << 5)
            + (quad << 2);

        float4 g00 = *(const float4*)(base);
        float4 g01 = *(const float4*)(base + FM_C);               // x+1: +128 B
        float4 g10 = *(const float4*)(base + FM_W * FM_C);        // y+1: +16 KB
        float4 g11 = *(const float4*)(base + FM_W * FM_C + FM_C); // both

        float w00 = (1.f - wy) * (1.f - wx);
        float w01 = (1.f - wy) * wx;
        float w10 = wy * (1.f - wx);
        float w11 = wy * wx;

        r.x = fmaf(w00, g00.x, fmaf(w01, g01.x, fmaf(w10, g10.x, w11 * g11.x)));
        r.y = fmaf(w00, g00.y, fmaf(w01, g01.y, fmaf(w10, g10.y, w11 * g11.y)));
        r.z = fmaf(w00, g00.z, fmaf(w01, g01.z, fmaf(w10, g10.z, w11 * g11.z)));
        r.w = fmaf(w00, g00.w, fmaf(w01, g01.w, fmaf(w10, g10.w, w11 * g11.w)));
    }

    // Coalesced streaming store: consecutive gid -> consecutive 16B chunks.
    __stcs((float4*)(out + (((size_t)pos) << 5) + (quad << 2)), r);
}

extern "C" void kernel_launch(void* const* d_in, const int* in_sizes, int n_in,
                              void* d_out, int out_size)
{
    const float* fm    = (const float*)d_in[0];
    const float* boxes = (const float*)d_in[1];
    const int*   bidx  = (const int*)d_in[2];
    float*       out   = (float*)d_out;

    box_prep_kernel<<<ROI_NBOX / 256, 256>>>(boxes, bidx, out);

    const int total = ROI_NBOX * ROI_HEIGHT * ROI_MAXW * (FM_C / 4); // 8,388,608
    roi_rotate_kernel<<<total / 256, 256>>>(fm, out);
}